// round 1
// baseline (speedup 1.0000x reference)
#include <cuda_runtime.h>
#include <math.h>

#define NN 50000
#define EE 800000
#define INF_ 128
#define HID 16
#define HEADS 8
#define F1 128   /* HEADS*HID */
#define CLS 40

// ---------------- scratch (static device allocations; no runtime alloc) ----
__device__ __align__(16) float g_feat1[NN * F1];     // layer1 x@W1
__device__ float g_el1[NN * HEADS];
__device__ float g_er1[NN * HEADS];
__device__ __align__(16) float g_h[NN * F1];         // elu(layer1 out)
__device__ __align__(16) float g_feat2[NN * CLS];    // h@W2
__device__ float g_el2[NN];
__device__ float g_er2[NN];
__device__ int   g_deg[NN];
__device__ int   g_cur[NN];
__device__ int   g_off[NN + 1];
__device__ int   g_csrc[EE];
__device__ float g_a1[EE * HEADS];                   // layer1 edge coeffs
__device__ float g_a2[EE];                           // layer2 edge coeffs

// ---------------- CSR build -------------------------------------------------
__global__ void k_zero() {
    int i = blockIdx.x * blockDim.x + threadIdx.x;
    if (i < NN) { g_deg[i] = 0; g_cur[i] = 0; }
}

__global__ void k_count(const int* __restrict__ dst) {
    int e = blockIdx.x * blockDim.x + threadIdx.x;
    if (e < EE) atomicAdd(&g_deg[dst[e]], 1);
}

// single-block exclusive prefix sum over g_deg -> g_off (warp-scan based)
__global__ void __launch_bounds__(1024) k_scan() {
    __shared__ int wsum[32];
    __shared__ int s_carry;
    int tid = threadIdx.x, lane = tid & 31, wid = tid >> 5;
    if (tid == 0) s_carry = 0;
    __syncthreads();
    for (int base = 0; base < NN; base += 1024) {
        int i = base + tid;
        int v = (i < NN) ? g_deg[i] : 0;
        int x = v;
        #pragma unroll
        for (int o = 1; o < 32; o <<= 1) {
            int y = __shfl_up_sync(0xffffffffu, x, o);
            if (lane >= o) x += y;
        }
        if (lane == 31) wsum[wid] = x;
        __syncthreads();
        if (wid == 0) {
            int y = wsum[lane];
            #pragma unroll
            for (int o = 1; o < 32; o <<= 1) {
                int z = __shfl_up_sync(0xffffffffu, y, o);
                if (lane >= o) y += z;
            }
            wsum[lane] = y;
        }
        __syncthreads();
        int carry = s_carry;
        int wofs = wid ? wsum[wid - 1] : 0;
        if (i < NN) g_off[i] = carry + wofs + x - v;
        __syncthreads();
        if (tid == 0) s_carry = carry + wsum[31];
        __syncthreads();
    }
    if (threadIdx.x == 0) g_off[NN] = s_carry;
}

__global__ void k_scatter(const int* __restrict__ src, const int* __restrict__ dst) {
    int e = blockIdx.x * blockDim.x + threadIdx.x;
    if (e >= EE) return;
    int d = dst[e];
    int pos = g_off[d] + atomicAdd(&g_cur[d], 1);
    g_csrc[pos] = src[e];
}

// ---------------- GEMM1: feat1 = X[N,128] @ W1[128,128] --------------------
__global__ void __launch_bounds__(128) k_gemm1(const float* __restrict__ X,
                                               const float* __restrict__ W) {
    __shared__ __align__(16) float Xs[32][65];
    __shared__ __align__(16) float Ws[64][128];
    int tid = threadIdx.x;
    int tr = tid >> 4, tc = tid & 15;
    int r0 = tr * 4, c0 = tc * 8;
    int row0 = blockIdx.x * 32;
    float acc[4][8];
    #pragma unroll
    for (int i = 0; i < 4; i++)
        #pragma unroll
        for (int j = 0; j < 8; j++) acc[i][j] = 0.f;

    for (int kc = 0; kc < 128; kc += 64) {
        #pragma unroll
        for (int i = tid; i < 32 * 64; i += 128) {
            int r = i >> 6, c = i & 63;
            int gr = row0 + r;
            Xs[r][c] = (gr < NN) ? X[gr * 128 + kc + c] : 0.f;
        }
        #pragma unroll 8
        for (int i = tid; i < 64 * 128; i += 128) {
            int r = i >> 7, c = i & 127;
            Ws[r][c] = W[(kc + r) * 128 + c];
        }
        __syncthreads();
        #pragma unroll 8
        for (int k = 0; k < 64; k++) {
            float4 w0 = *(const float4*)&Ws[k][c0];
            float4 w1 = *(const float4*)&Ws[k][c0 + 4];
            #pragma unroll
            for (int i = 0; i < 4; i++) {
                float x = Xs[r0 + i][k];
                acc[i][0] += x * w0.x; acc[i][1] += x * w0.y;
                acc[i][2] += x * w0.z; acc[i][3] += x * w0.w;
                acc[i][4] += x * w1.x; acc[i][5] += x * w1.y;
                acc[i][6] += x * w1.z; acc[i][7] += x * w1.w;
            }
        }
        __syncthreads();
    }
    #pragma unroll
    for (int i = 0; i < 4; i++) {
        int gr = row0 + r0 + i;
        if (gr < NN) {
            *(float4*)&g_feat1[gr * 128 + c0] =
                make_float4(acc[i][0], acc[i][1], acc[i][2], acc[i][3]);
            *(float4*)&g_feat1[gr * 128 + c0 + 4] =
                make_float4(acc[i][4], acc[i][5], acc[i][6], acc[i][7]);
        }
    }
}

// ---------------- layer1 attention coefficients ----------------------------
__global__ void k_coef1(const float* __restrict__ al, const float* __restrict__ ar) {
    int i = blockIdx.x * blockDim.x + threadIdx.x;
    if (i >= NN * HEADS) return;
    int h = i & 7;
    int v = i >> 3;
    const float* f = g_feat1 + v * 128 + h * 16;
    float el = 0.f, er = 0.f;
    #pragma unroll
    for (int j = 0; j < 16; j++) {
        float x = f[j];
        el += x * al[h * 16 + j];
        er += x * ar[h * 16 + j];
    }
    g_el1[i] = el;
    g_er1[i] = er;
}

// ---------------- layer1 node aggregation (one warp per dst node) ----------
__global__ void __launch_bounds__(256) k_node1(const float* __restrict__ b1) {
    int gw = (blockIdx.x * blockDim.x + threadIdx.x) >> 5;
    if (gw >= NN) return;
    int lane = threadIdx.x & 31;
    int v = gw;
    int beg = g_off[v], end = g_off[v + 1];

    float er[HEADS], m[HEADS], ss[HEADS];
    #pragma unroll
    for (int h = 0; h < HEADS; h++) {
        er[h] = g_er1[v * 8 + h];
        m[h] = -1e30f;
        ss[h] = 0.f;
    }
    // pass 1: e = leakyrelu(el[src]+er[v]); per-head max
    for (int p = beg + lane; p < end; p += 32) {
        int s = g_csrc[p];
        #pragma unroll
        for (int h = 0; h < HEADS; h++) {
            float e = g_el1[s * 8 + h] + er[h];
            e = (e > 0.f) ? e : 0.2f * e;
            g_a1[p * 8 + h] = e;
            m[h] = fmaxf(m[h], e);
        }
    }
    #pragma unroll
    for (int h = 0; h < HEADS; h++)
        #pragma unroll
        for (int o = 16; o; o >>= 1)
            m[h] = fmaxf(m[h], __shfl_xor_sync(0xffffffffu, m[h], o));
    // pass 2: ee = exp(e - m); per-head sum
    for (int p = beg + lane; p < end; p += 32) {
        #pragma unroll
        for (int h = 0; h < HEADS; h++) {
            float ee = __expf(g_a1[p * 8 + h] - m[h]);
            g_a1[p * 8 + h] = ee;
            ss[h] += ee;
        }
    }
    #pragma unroll
    for (int h = 0; h < HEADS; h++)
        #pragma unroll
        for (int o = 16; o; o >>= 1)
            ss[h] += __shfl_xor_sync(0xffffffffu, ss[h], o);

    // lane owns 4 output dims: dims [4*lane, 4*lane+4), head = lane>>2
    int h4 = lane >> 2;
    float sel = ss[0];
    #pragma unroll
    for (int h = 1; h < HEADS; h++)
        if (h4 == h) sel = ss[h];
    float myinv = 1.f / (sel + 1e-9f);

    float4 acc = make_float4(0.f, 0.f, 0.f, 0.f);
    for (int p = beg; p < end; p++) {
        int s = g_csrc[p];                       // broadcast
        float w = g_a1[p * 8 + h4] * myinv;
        float4 f = *(const float4*)&g_feat1[s * 128 + lane * 4];
        acc.x += w * f.x; acc.y += w * f.y;
        acc.z += w * f.z; acc.w += w * f.w;
    }
    float4 b = *(const float4*)&b1[lane * 4];
    float4 r;
    r.x = acc.x + b.x; r.y = acc.y + b.y;
    r.z = acc.z + b.z; r.w = acc.w + b.w;
    r.x = (r.x > 0.f) ? r.x : expm1f(r.x);
    r.y = (r.y > 0.f) ? r.y : expm1f(r.y);
    r.z = (r.z > 0.f) ? r.z : expm1f(r.z);
    r.w = (r.w > 0.f) ? r.w : expm1f(r.w);
    *(float4*)&g_h[v * 128 + lane * 4] = r;
}

// ---------------- GEMM2: feat2 = h[N,128] @ W2[128,40] ---------------------
__global__ void __launch_bounds__(240) k_gemm2(const float* __restrict__ W) {
    __shared__ __align__(16) float Xs[48][129];
    __shared__ __align__(16) float Ws[128][40];
    int tid = threadIdx.x;
    int tc = tid % 10, rl = tid / 10;       // rl in [0,24)
    int row0 = blockIdx.x * 48;
    for (int i = tid; i < 48 * 128; i += 240) {
        int r = i >> 7, c = i & 127;
        int gr = row0 + r;
        Xs[r][c] = (gr < NN) ? g_h[gr * 128 + c] : 0.f;
    }
    for (int i = tid; i < 128 * 40; i += 240)
        Ws[i / 40][i % 40] = W[i];
    __syncthreads();

    float a0[4] = {0, 0, 0, 0}, a1[4] = {0, 0, 0, 0};
    #pragma unroll 4
    for (int k = 0; k < 128; k++) {
        float4 w = *(const float4*)&Ws[k][tc * 4];
        float xa = Xs[rl][k];
        float xb = Xs[rl + 24][k];
        a0[0] += xa * w.x; a0[1] += xa * w.y; a0[2] += xa * w.z; a0[3] += xa * w.w;
        a1[0] += xb * w.x; a1[1] += xb * w.y; a1[2] += xb * w.z; a1[3] += xb * w.w;
    }
    int ra = row0 + rl, rb = ra + 24;
    if (ra < NN)
        *(float4*)&g_feat2[ra * 40 + tc * 4] = make_float4(a0[0], a0[1], a0[2], a0[3]);
    if (rb < NN)
        *(float4*)&g_feat2[rb * 40 + tc * 4] = make_float4(a1[0], a1[1], a1[2], a1[3]);
}

// ---------------- layer2 attention coefficients ----------------------------
__global__ void k_coef2(const float* __restrict__ al, const float* __restrict__ ar) {
    int v = blockIdx.x * blockDim.x + threadIdx.x;
    if (v >= NN) return;
    const float* f = g_feat2 + v * 40;
    float el = 0.f, er = 0.f;
    #pragma unroll
    for (int j = 0; j < 40; j++) {
        float x = f[j];
        el += x * al[j];
        er += x * ar[j];
    }
    g_el2[v] = el;
    g_er2[v] = er;
}

// ---------------- layer2 node aggregation (one warp per dst node) ----------
__global__ void __launch_bounds__(256) k_node2(const float* __restrict__ b2,
                                               float* __restrict__ out) {
    int gw = (blockIdx.x * blockDim.x + threadIdx.x) >> 5;
    if (gw >= NN) return;
    int lane = threadIdx.x & 31;
    int v = gw;
    int beg = g_off[v], end = g_off[v + 1];
    float erv = g_er2[v];

    float m = -1e30f;
    for (int p = beg + lane; p < end; p += 32) {
        int s = g_csrc[p];
        float e = g_el2[s] + erv;
        e = (e > 0.f) ? e : 0.2f * e;
        g_a2[p] = e;
        m = fmaxf(m, e);
    }
    #pragma unroll
    for (int o = 16; o; o >>= 1)
        m = fmaxf(m, __shfl_xor_sync(0xffffffffu, m, o));

    float ssum = 0.f;
    for (int p = beg + lane; p < end; p += 32) {
        float ee = __expf(g_a2[p] - m);
        g_a2[p] = ee;
        ssum += ee;
    }
    #pragma unroll
    for (int o = 16; o; o >>= 1)
        ssum += __shfl_xor_sync(0xffffffffu, ssum, o);
    float inv = 1.f / (ssum + 1e-9f);

    float acc0 = 0.f, acc1 = 0.f;
    for (int p = beg; p < end; p++) {
        int s = g_csrc[p];
        float w = g_a2[p] * inv;
        acc0 += w * g_feat2[s * 40 + lane];
        if (lane < 8) acc1 += w * g_feat2[s * 40 + 32 + lane];
    }
    out[v * 40 + lane] = acc0 + b2[lane];
    if (lane < 8) out[v * 40 + 32 + lane] = acc1 + b2[32 + lane];
}

// ---------------- launch ----------------------------------------------------
extern "C" void kernel_launch(void* const* d_in, const int* in_sizes, int n_in,
                              void* d_out, int out_size) {
    const float* features = (const float*)d_in[0];
    const int*   esrc     = (const int*)d_in[1];
    const int*   edst     = (const int*)d_in[2];
    const float* W1       = (const float*)d_in[3];
    const float* al1      = (const float*)d_in[4];
    const float* ar1      = (const float*)d_in[5];
    const float* b1       = (const float*)d_in[6];
    const float* W2       = (const float*)d_in[7];
    const float* al2      = (const float*)d_in[8];
    const float* ar2      = (const float*)d_in[9];
    const float* b2       = (const float*)d_in[10];
    float* out = (float*)d_out;

    k_zero<<<(NN + 255) / 256, 256>>>();
    k_count<<<(EE + 255) / 256, 256>>>(edst);
    k_scan<<<1, 1024>>>();
    k_scatter<<<(EE + 255) / 256, 256>>>(esrc, edst);

    k_gemm1<<<(NN + 31) / 32, 128>>>(features, W1);
    k_coef1<<<(NN * HEADS + 255) / 256, 256>>>(al1, ar1);
    k_node1<<<(NN * 32 + 255) / 256, 256>>>(b1);

    k_gemm2<<<(NN + 47) / 48, 240>>>(W2);
    k_coef2<<<(NN + 255) / 256, 256>>>(al2, ar2);
    k_node2<<<(NN * 32 + 255) / 256, 256>>>(b2, out);
}

// round 3
// speedup vs baseline: 1.0403x; 1.0403x over previous
#include <cuda_runtime.h>
#include <math.h>

#define NN 50000
#define EE 800000
#define HID 16
#define HEADS 8
#define F1 128   /* HEADS*HID */
#define CLS 40

// ---------------- scratch ----------------------------------------------------
__device__ __align__(16) float g_feat1[NN * F1];     // layer1 x@W1
__device__ float g_el1[NN * HEADS];
__device__ float g_er1[NN * HEADS];
__device__ __align__(16) float g_h[NN * F1];         // elu(layer1 out)
__device__ __align__(16) float g_feat2[NN * CLS];    // h@W2
__device__ float g_el2[NN];
__device__ float g_er2[NN];
__device__ int   g_deg[NN];
__device__ int   g_cur[NN];
__device__ int   g_off[NN + 1];
__device__ int   g_csrc[EE];

#define ESTRIDE ((EE + 3) / 4)

// ---------------- CSR build --------------------------------------------------
__global__ void k_zero() {
    int i = blockIdx.x * blockDim.x + threadIdx.x;
    if (i < NN) { g_deg[i] = 0; g_cur[i] = 0; }
}

__global__ void k_count(const int* __restrict__ dst) {
    int t = blockIdx.x * blockDim.x + threadIdx.x;
    if (t >= ESTRIDE) return;                 // each edge owned by exactly one thread
    #pragma unroll
    for (int j = 0; j < 4; j++) {
        int e = t + j * ESTRIDE;
        if (e < EE) atomicAdd(&g_deg[dst[e]], 1);
    }
}

// single-block exclusive prefix sum over g_deg -> g_off
__global__ void __launch_bounds__(1024) k_scan() {
    __shared__ int wsum[32];
    __shared__ int s_carry;
    int tid = threadIdx.x, lane = tid & 31, wid = tid >> 5;
    if (tid == 0) s_carry = 0;
    __syncthreads();
    for (int base = 0; base < NN; base += 1024) {
        int i = base + tid;
        int v = (i < NN) ? g_deg[i] : 0;
        int x = v;
        #pragma unroll
        for (int o = 1; o < 32; o <<= 1) {
            int y = __shfl_up_sync(0xffffffffu, x, o);
            if (lane >= o) x += y;
        }
        if (lane == 31) wsum[wid] = x;
        __syncthreads();
        if (wid == 0) {
            int y = wsum[lane];
            #pragma unroll
            for (int o = 1; o < 32; o <<= 1) {
                int z = __shfl_up_sync(0xffffffffu, y, o);
                if (lane >= o) y += z;
            }
            wsum[lane] = y;
        }
        __syncthreads();
        int carry = s_carry;
        int wofs = wid ? wsum[wid - 1] : 0;
        if (i < NN) g_off[i] = carry + wofs + x - v;
        __syncthreads();
        if (tid == 0) s_carry = carry + wsum[31];
        __syncthreads();
    }
    if (threadIdx.x == 0) g_off[NN] = s_carry;
}

__global__ void k_scatter(const int* __restrict__ src, const int* __restrict__ dst) {
    int t = blockIdx.x * blockDim.x + threadIdx.x;
    if (t >= ESTRIDE) return;                 // each edge owned by exactly one thread
    int e0 = t, e1 = t + ESTRIDE, e2 = t + 2 * ESTRIDE, e3 = t + 3 * ESTRIDE;
    int d0 = (e0 < EE) ? dst[e0] : 0;
    int d1 = (e1 < EE) ? dst[e1] : 0;
    int d2 = (e2 < EE) ? dst[e2] : 0;
    int d3 = (e3 < EE) ? dst[e3] : 0;
    int s0 = (e0 < EE) ? src[e0] : 0;
    int s1 = (e1 < EE) ? src[e1] : 0;
    int s2 = (e2 < EE) ? src[e2] : 0;
    int s3 = (e3 < EE) ? src[e3] : 0;
    if (e0 < EE) g_csrc[g_off[d0] + atomicAdd(&g_cur[d0], 1)] = s0;
    if (e1 < EE) g_csrc[g_off[d1] + atomicAdd(&g_cur[d1], 1)] = s1;
    if (e2 < EE) g_csrc[g_off[d2] + atomicAdd(&g_cur[d2], 1)] = s2;
    if (e3 < EE) g_csrc[g_off[d3] + atomicAdd(&g_cur[d3], 1)] = s3;
}

// ---------------- GEMM1 + fused attention-coefficient epilogue ---------------
// feat1 = X[N,128] @ W1[128,128]; el1/er1 = per-head dot(feat1, al/ar)
__global__ void __launch_bounds__(128) k_gemm1(const float* __restrict__ X,
                                               const float* __restrict__ W,
                                               const float* __restrict__ al,
                                               const float* __restrict__ ar) {
    __shared__ __align__(16) float Xs[32][65];
    __shared__ __align__(16) float Ws[64][128];
    int tid = threadIdx.x;
    int tr = tid >> 4, tc = tid & 15;
    int r0 = tr * 4, c0 = tc * 8;
    int row0 = blockIdx.x * 32;
    float acc[4][8];
    #pragma unroll
    for (int i = 0; i < 4; i++)
        #pragma unroll
        for (int j = 0; j < 8; j++) acc[i][j] = 0.f;

    for (int kc = 0; kc < 128; kc += 64) {
        #pragma unroll
        for (int i = tid; i < 32 * 64; i += 128) {
            int r = i >> 6, c = i & 63;
            int gr = row0 + r;
            Xs[r][c] = (gr < NN) ? X[gr * 128 + kc + c] : 0.f;
        }
        #pragma unroll 8
        for (int i = tid; i < 64 * 128; i += 128) {
            int r = i >> 7, c = i & 127;
            Ws[r][c] = W[(kc + r) * 128 + c];
        }
        __syncthreads();
        #pragma unroll 8
        for (int k = 0; k < 64; k++) {
            float4 w0 = *(const float4*)&Ws[k][c0];
            float4 w1 = *(const float4*)&Ws[k][c0 + 4];
            #pragma unroll
            for (int i = 0; i < 4; i++) {
                float x = Xs[r0 + i][k];
                acc[i][0] += x * w0.x; acc[i][1] += x * w0.y;
                acc[i][2] += x * w0.z; acc[i][3] += x * w0.w;
                acc[i][4] += x * w1.x; acc[i][5] += x * w1.y;
                acc[i][6] += x * w1.z; acc[i][7] += x * w1.w;
            }
        }
        __syncthreads();
    }

    // store feat1
    #pragma unroll
    for (int i = 0; i < 4; i++) {
        int gr = row0 + r0 + i;
        if (gr < NN) {
            *(float4*)&g_feat1[gr * 128 + c0] =
                make_float4(acc[i][0], acc[i][1], acc[i][2], acc[i][3]);
            *(float4*)&g_feat1[gr * 128 + c0 + 4] =
                make_float4(acc[i][4], acc[i][5], acc[i][6], acc[i][7]);
        }
    }

    // fused el/er: thread covers 8 of its head's 16 dims; pair via shfl_xor(1)
    int h = tc >> 1;
    int ofs = (tc & 1) * 8;
    float4 alo = *(const float4*)&al[h * 16 + ofs];
    float4 ahi = *(const float4*)&al[h * 16 + ofs + 4];
    float4 rlo = *(const float4*)&ar[h * 16 + ofs];
    float4 rhi = *(const float4*)&ar[h * 16 + ofs + 4];
    #pragma unroll
    for (int i = 0; i < 4; i++) {
        float el = acc[i][0] * alo.x + acc[i][1] * alo.y + acc[i][2] * alo.z +
                   acc[i][3] * alo.w + acc[i][4] * ahi.x + acc[i][5] * ahi.y +
                   acc[i][6] * ahi.z + acc[i][7] * ahi.w;
        float er = acc[i][0] * rlo.x + acc[i][1] * rlo.y + acc[i][2] * rlo.z +
                   acc[i][3] * rlo.w + acc[i][4] * rhi.x + acc[i][5] * rhi.y +
                   acc[i][6] * rhi.z + acc[i][7] * rhi.w;
        el += __shfl_xor_sync(0xffffffffu, el, 1);
        er += __shfl_xor_sync(0xffffffffu, er, 1);
        int gr = row0 + r0 + i;
        if (((tc & 1) == 0) && gr < NN) {
            g_el1[gr * 8 + h] = el;
            g_er1[gr * 8 + h] = er;
        }
    }
}

// ---------------- layer1 fused softmax+aggregate (one warp per dst) ----------
// alpha = exp(e)/sum(exp(e)) computed without max-shift (identical ratio).
__global__ void __launch_bounds__(256) k_node1(const float* __restrict__ b1) {
    int v = (blockIdx.x * blockDim.x + threadIdx.x) >> 5;
    if (v >= NN) return;
    int lane = threadIdx.x & 31;
    int h4 = lane >> 2;                       // head owned by this lane
    int beg = g_off[v], end = g_off[v + 1];
    float erh = g_er1[v * 8 + h4];

    float denom = 0.f;
    float4 acc = make_float4(0.f, 0.f, 0.f, 0.f);
    int p = beg;
    int s = (p < end) ? g_csrc[p] : 0;
    while (p < end) {
        int sn = (p + 1 < end) ? g_csrc[p + 1] : 0;   // prefetch
        float e = g_el1[s * 8 + h4] + erh;
        e = (e > 0.f) ? e : 0.2f * e;
        float w = __expf(e);
        float4 f = *(const float4*)&g_feat1[s * 128 + lane * 4];
        denom += w;
        acc.x += w * f.x; acc.y += w * f.y;
        acc.z += w * f.z; acc.w += w * f.w;
        s = sn; ++p;
    }
    float inv = 1.f / (denom + 1e-9f);
    float4 b = *(const float4*)&b1[lane * 4];
    float4 r;
    r.x = acc.x * inv + b.x; r.y = acc.y * inv + b.y;
    r.z = acc.z * inv + b.z; r.w = acc.w * inv + b.w;
    r.x = (r.x > 0.f) ? r.x : expm1f(r.x);
    r.y = (r.y > 0.f) ? r.y : expm1f(r.y);
    r.z = (r.z > 0.f) ? r.z : expm1f(r.z);
    r.w = (r.w > 0.f) ? r.w : expm1f(r.w);
    *(float4*)&g_h[v * 128 + lane * 4] = r;
}

// ---------------- GEMM2: feat2 = h[N,128] @ W2[128,40] -----------------------
__global__ void __launch_bounds__(240) k_gemm2(const float* __restrict__ W) {
    __shared__ __align__(16) float Xs[48][129];
    __shared__ __align__(16) float Ws[128][40];
    int tid = threadIdx.x;
    int tc = tid % 10, rl = tid / 10;
    int row0 = blockIdx.x * 48;
    for (int i = tid; i < 48 * 128; i += 240) {
        int r = i >> 7, c = i & 127;
        int gr = row0 + r;
        Xs[r][c] = (gr < NN) ? g_h[gr * 128 + c] : 0.f;
    }
    for (int i = tid; i < 128 * 40; i += 240)
        Ws[i / 40][i % 40] = W[i];
    __syncthreads();

    float a0[4] = {0, 0, 0, 0}, a1[4] = {0, 0, 0, 0};
    #pragma unroll 4
    for (int k = 0; k < 128; k++) {
        float4 w = *(const float4*)&Ws[k][tc * 4];
        float xa = Xs[rl][k];
        float xb = Xs[rl + 24][k];
        a0[0] += xa * w.x; a0[1] += xa * w.y; a0[2] += xa * w.z; a0[3] += xa * w.w;
        a1[0] += xb * w.x; a1[1] += xb * w.y; a1[2] += xb * w.z; a1[3] += xb * w.w;
    }
    int ra = row0 + rl, rb = ra + 24;
    if (ra < NN)
        *(float4*)&g_feat2[ra * 40 + tc * 4] = make_float4(a0[0], a0[1], a0[2], a0[3]);
    if (rb < NN)
        *(float4*)&g_feat2[rb * 40 + tc * 4] = make_float4(a1[0], a1[1], a1[2], a1[3]);
}

// ---------------- layer2 attention coefficients ------------------------------
__global__ void k_coef2(const float* __restrict__ al, const float* __restrict__ ar) {
    int v = blockIdx.x * blockDim.x + threadIdx.x;
    if (v >= NN) return;
    const float* f = g_feat2 + v * 40;
    float el = 0.f, er = 0.f;
    #pragma unroll
    for (int j = 0; j < 40; j++) {
        float x = f[j];
        el += x * al[j];
        er += x * ar[j];
    }
    g_el2[v] = el;
    g_er2[v] = er;
}

// ---------------- layer2 fused softmax+aggregate (one warp per dst) ----------
__global__ void __launch_bounds__(256) k_node2(const float* __restrict__ b2,
                                               float* __restrict__ out) {
    int v = (blockIdx.x * blockDim.x + threadIdx.x) >> 5;
    if (v >= NN) return;
    int lane = threadIdx.x & 31;
    int beg = g_off[v], end = g_off[v + 1];
    float erv = g_er2[v];

    float denom = 0.f, acc0 = 0.f, acc1 = 0.f;
    int p = beg;
    int s = (p < end) ? g_csrc[p] : 0;
    while (p < end) {
        int sn = (p + 1 < end) ? g_csrc[p + 1] : 0;   // prefetch
        float e = g_el2[s] + erv;
        e = (e > 0.f) ? e : 0.2f * e;
        float w = __expf(e);
        denom += w;
        acc0 += w * g_feat2[s * 40 + lane];
        if (lane < 8) acc1 += w * g_feat2[s * 40 + 32 + lane];
        s = sn; ++p;
    }
    float inv = 1.f / (denom + 1e-9f);
    out[v * 40 + lane] = acc0 * inv + b2[lane];
    if (lane < 8) out[v * 40 + 32 + lane] = acc1 * inv + b2[32 + lane];
}

// ---------------- launch ------------------------------------------------------
extern "C" void kernel_launch(void* const* d_in, const int* in_sizes, int n_in,
                              void* d_out, int out_size) {
    const float* features = (const float*)d_in[0];
    const int*   esrc     = (const int*)d_in[1];
    const int*   edst     = (const int*)d_in[2];
    const float* W1       = (const float*)d_in[3];
    const float* al1      = (const float*)d_in[4];
    const float* ar1      = (const float*)d_in[5];
    const float* b1       = (const float*)d_in[6];
    const float* W2       = (const float*)d_in[7];
    const float* al2      = (const float*)d_in[8];
    const float* ar2      = (const float*)d_in[9];
    const float* b2       = (const float*)d_in[10];
    float* out = (float*)d_out;

    k_zero<<<(NN + 255) / 256, 256>>>();
    k_count<<<(ESTRIDE + 255) / 256, 256>>>(edst);
    k_scan<<<1, 1024>>>();
    k_scatter<<<(ESTRIDE + 255) / 256, 256>>>(esrc, edst);

    k_gemm1<<<(NN + 31) / 32, 128>>>(features, W1, al1, ar1);
    k_node1<<<(NN * 32 + 255) / 256, 256>>>(b1);

    k_gemm2<<<(NN + 47) / 48, 240>>>(W2);
    k_coef2<<<(NN + 255) / 256, 256>>>(al2, ar2);
    k_node2<<<(NN * 32 + 255) / 256, 256>>>(b2, out);
}

// round 4
// speedup vs baseline: 1.3269x; 1.2755x over previous
#include <cuda_runtime.h>
#include <math.h>

#define NN 50000
#define EE 800000
#define HID 16
#define HEADS 8
#define F1 128   /* HEADS*HID */
#define CLS 40
#define SCAN_B 512
#define NSB ((NN + SCAN_B - 1) / SCAN_B)   /* 98 */

// ---------------- scratch ----------------------------------------------------
__device__ __align__(16) float g_feat1[NN * F1];     // layer1 x@W1
__device__ float g_el1[NN * HEADS];
__device__ float g_er1[NN * HEADS];
__device__ __align__(16) float g_h[NN * F1];         // elu(layer1 out)
__device__ __align__(16) float g_feat2[NN * CLS];    // h@W2
__device__ float g_el2[NN];
__device__ float g_er2[NN];
__device__ int   g_deg[NN];
__device__ int   g_cur[NN];
__device__ int   g_off[NN + 1];
__device__ int   g_bsum[NSB];
__device__ int   g_bofs[NSB];
__device__ int   g_csrc[EE];

// ---------------- CSR build --------------------------------------------------
__global__ void k_zero() {
    int i = blockIdx.x * blockDim.x + threadIdx.x;
    if (i < NN) { g_deg[i] = 0; g_cur[i] = 0; }
}

// 4 consecutive edges per thread via int4 (EE % 4 == 0)
__global__ void k_count(const int* __restrict__ dst) {
    int t = blockIdx.x * blockDim.x + threadIdx.x;
    if (t >= EE / 4) return;
    int4 d = ((const int4*)dst)[t];
    atomicAdd(&g_deg[d.x], 1);
    atomicAdd(&g_deg[d.y], 1);
    atomicAdd(&g_deg[d.z], 1);
    atomicAdd(&g_deg[d.w], 1);
}

// ---- multi-block exclusive scan: A (per-block), B (block sums), C (add) -----
__global__ void __launch_bounds__(SCAN_B) k_scanA() {
    __shared__ int wsum[16];
    int tid = threadIdx.x, lane = tid & 31, wid = tid >> 5;
    int i = blockIdx.x * SCAN_B + tid;
    int v = (i < NN) ? g_deg[i] : 0;
    int x = v;
    #pragma unroll
    for (int o = 1; o < 32; o <<= 1) {
        int y = __shfl_up_sync(0xffffffffu, x, o);
        if (lane >= o) x += y;
    }
    if (lane == 31) wsum[wid] = x;
    __syncthreads();
    if (wid == 0 && lane < 16) {
        int y = wsum[lane];
        #pragma unroll
        for (int o = 1; o < 16; o <<= 1) {
            int z = __shfl_up_sync(0x0000ffffu, y, o);
            if (lane >= o) y += z;
        }
        wsum[lane] = y;
    }
    __syncthreads();
    int wofs = wid ? wsum[wid - 1] : 0;
    if (i < NN) g_off[i] = wofs + x - v;
    if (tid == SCAN_B - 1) g_bsum[blockIdx.x] = wofs + x;
}

__global__ void k_scanB() {   // 1 warp scans NSB block sums
    int lane = threadIdx.x;
    int carry = 0;
    #pragma unroll
    for (int c = 0; c < (NSB + 31) / 32; c++) {
        int i = c * 32 + lane;
        int v = (i < NSB) ? g_bsum[i] : 0;
        int x = v;
        #pragma unroll
        for (int o = 1; o < 32; o <<= 1) {
            int y = __shfl_up_sync(0xffffffffu, x, o);
            if (lane >= o) x += y;
        }
        if (i < NSB) g_bofs[i] = carry + x - v;
        carry += __shfl_sync(0xffffffffu, x, 31);
    }
}

__global__ void k_scanC() {
    int i = blockIdx.x * blockDim.x + threadIdx.x;
    if (i < NN) g_off[i] += g_bofs[i / SCAN_B];
    if (i == 0) g_off[NN] = EE;
}

__global__ void k_scatter(const int* __restrict__ src, const int* __restrict__ dst) {
    int t = blockIdx.x * blockDim.x + threadIdx.x;
    if (t >= EE / 4) return;
    int4 d = ((const int4*)dst)[t];
    int4 s = ((const int4*)src)[t];
    g_csrc[g_off[d.x] + atomicAdd(&g_cur[d.x], 1)] = s.x;
    g_csrc[g_off[d.y] + atomicAdd(&g_cur[d.y], 1)] = s.y;
    g_csrc[g_off[d.z] + atomicAdd(&g_cur[d.z], 1)] = s.z;
    g_csrc[g_off[d.w] + atomicAdd(&g_cur[d.w], 1)] = s.w;
}

// ---------------- GEMM1 (64 rows/block) + fused el/er epilogue ---------------
__global__ void __launch_bounds__(256) k_gemm1(const float* __restrict__ X,
                                               const float* __restrict__ W,
                                               const float* __restrict__ al,
                                               const float* __restrict__ ar) {
    __shared__ __align__(16) float Xs[64][65];
    __shared__ __align__(16) float Ws[64][128];
    int tid = threadIdx.x;
    int tr = tid >> 4, tc = tid & 15;
    int r0 = tr * 4, c0 = tc * 8;
    int row0 = blockIdx.x * 64;
    float acc[4][8];
    #pragma unroll
    for (int i = 0; i < 4; i++)
        #pragma unroll
        for (int j = 0; j < 8; j++) acc[i][j] = 0.f;

    for (int kc = 0; kc < 128; kc += 64) {
        // X: 64 rows x 64 cols, float4 loads (1024 float4 / 256 thr = 4 each)
        #pragma unroll
        for (int i = tid; i < 1024; i += 256) {
            int r = i >> 4, c4 = (i & 15) * 4;
            int gr = row0 + r;
            float4 v = (gr < NN) ? *(const float4*)&X[gr * 128 + kc + c4]
                                 : make_float4(0.f, 0.f, 0.f, 0.f);
            Xs[r][c4] = v.x; Xs[r][c4 + 1] = v.y;
            Xs[r][c4 + 2] = v.z; Xs[r][c4 + 3] = v.w;
        }
        // W: 64 rows x 128 cols (2048 float4 / 256 thr = 8 each)
        #pragma unroll
        for (int i = tid; i < 2048; i += 256) {
            int r = i >> 5, c4 = (i & 31) * 4;
            *(float4*)&Ws[r][c4] = *(const float4*)&W[(kc + r) * 128 + c4];
        }
        __syncthreads();
        #pragma unroll 8
        for (int k = 0; k < 64; k++) {
            float4 w0 = *(const float4*)&Ws[k][c0];
            float4 w1 = *(const float4*)&Ws[k][c0 + 4];
            #pragma unroll
            for (int i = 0; i < 4; i++) {
                float x = Xs[r0 + i][k];
                acc[i][0] += x * w0.x; acc[i][1] += x * w0.y;
                acc[i][2] += x * w0.z; acc[i][3] += x * w0.w;
                acc[i][4] += x * w1.x; acc[i][5] += x * w1.y;
                acc[i][6] += x * w1.z; acc[i][7] += x * w1.w;
            }
        }
        __syncthreads();
    }

    #pragma unroll
    for (int i = 0; i < 4; i++) {
        int gr = row0 + r0 + i;
        if (gr < NN) {
            *(float4*)&g_feat1[gr * 128 + c0] =
                make_float4(acc[i][0], acc[i][1], acc[i][2], acc[i][3]);
            *(float4*)&g_feat1[gr * 128 + c0 + 4] =
                make_float4(acc[i][4], acc[i][5], acc[i][6], acc[i][7]);
        }
    }

    // fused el/er: thread covers 8 of its head's 16 dims; pair via shfl_xor(1)
    int h = tc >> 1;
    int ofs = (tc & 1) * 8;
    float4 alo = *(const float4*)&al[h * 16 + ofs];
    float4 ahi = *(const float4*)&al[h * 16 + ofs + 4];
    float4 rlo = *(const float4*)&ar[h * 16 + ofs];
    float4 rhi = *(const float4*)&ar[h * 16 + ofs + 4];
    #pragma unroll
    for (int i = 0; i < 4; i++) {
        float el = acc[i][0] * alo.x + acc[i][1] * alo.y + acc[i][2] * alo.z +
                   acc[i][3] * alo.w + acc[i][4] * ahi.x + acc[i][5] * ahi.y +
                   acc[i][6] * ahi.z + acc[i][7] * ahi.w;
        float er = acc[i][0] * rlo.x + acc[i][1] * rlo.y + acc[i][2] * rlo.z +
                   acc[i][3] * rlo.w + acc[i][4] * rhi.x + acc[i][5] * rhi.y +
                   acc[i][6] * rhi.z + acc[i][7] * rhi.w;
        el += __shfl_xor_sync(0xffffffffu, el, 1);
        er += __shfl_xor_sync(0xffffffffu, er, 1);
        int gr = row0 + r0 + i;
        if (((tc & 1) == 0) && gr < NN) {
            g_el1[gr * 8 + h] = el;
            g_er1[gr * 8 + h] = er;
        }
    }
}

// ---------------- layer1 fused softmax+aggregate (one warp per dst) ----------
__global__ void __launch_bounds__(256) k_node1(const float* __restrict__ b1) {
    int v = (blockIdx.x * blockDim.x + threadIdx.x) >> 5;
    if (v >= NN) return;
    int lane = threadIdx.x & 31;
    int h4 = lane >> 2;
    int beg = g_off[v], end = g_off[v + 1];
    float erh = g_er1[v * 8 + h4];

    float denom = 0.f;
    float4 acc = make_float4(0.f, 0.f, 0.f, 0.f);
    // 2-deep software pipeline: stage next edge's el + feature row
    int s0 = (beg < end) ? g_csrc[beg] : 0;
    float eln = (beg < end) ? g_el1[s0 * 8 + h4] : 0.f;
    float4 fn = (beg < end) ? *(const float4*)&g_feat1[s0 * 128 + lane * 4]
                            : make_float4(0.f, 0.f, 0.f, 0.f);
    for (int p = beg; p < end; p++) {
        float elc = eln;
        float4 fc = fn;
        int sn = (p + 1 < end) ? g_csrc[p + 1] : 0;
        if (p + 1 < end) {
            eln = g_el1[sn * 8 + h4];
            fn = *(const float4*)&g_feat1[sn * 128 + lane * 4];
        }
        float e = elc + erh;
        e = (e > 0.f) ? e : 0.2f * e;
        float w = __expf(e);
        denom += w;
        acc.x += w * fc.x; acc.y += w * fc.y;
        acc.z += w * fc.z; acc.w += w * fc.w;
    }
    float inv = 1.f / (denom + 1e-9f);
    float4 b = *(const float4*)&b1[lane * 4];
    float4 r;
    r.x = acc.x * inv + b.x; r.y = acc.y * inv + b.y;
    r.z = acc.z * inv + b.z; r.w = acc.w * inv + b.w;
    r.x = (r.x > 0.f) ? r.x : expm1f(r.x);
    r.y = (r.y > 0.f) ? r.y : expm1f(r.y);
    r.z = (r.z > 0.f) ? r.z : expm1f(r.z);
    r.w = (r.w > 0.f) ? r.w : expm1f(r.w);
    *(float4*)&g_h[v * 128 + lane * 4] = r;
}

// ---------------- GEMM2: feat2 = h[N,128] @ W2[128,40] -----------------------
__global__ void __launch_bounds__(240) k_gemm2(const float* __restrict__ W) {
    __shared__ __align__(16) float Xs[48][129];
    __shared__ __align__(16) float Ws[128][40];
    int tid = threadIdx.x;
    int tc = tid % 10, rl = tid / 10;
    int row0 = blockIdx.x * 48;
    for (int i = tid; i < 48 * 128; i += 240) {
        int r = i >> 7, c = i & 127;
        int gr = row0 + r;
        Xs[r][c] = (gr < NN) ? g_h[gr * 128 + c] : 0.f;
    }
    for (int i = tid; i < 128 * 40; i += 240)
        Ws[i / 40][i % 40] = W[i];
    __syncthreads();

    float a0[4] = {0, 0, 0, 0}, a1[4] = {0, 0, 0, 0};
    #pragma unroll 4
    for (int k = 0; k < 128; k++) {
        float4 w = *(const float4*)&Ws[k][tc * 4];
        float xa = Xs[rl][k];
        float xb = Xs[rl + 24][k];
        a0[0] += xa * w.x; a0[1] += xa * w.y; a0[2] += xa * w.z; a0[3] += xa * w.w;
        a1[0] += xb * w.x; a1[1] += xb * w.y; a1[2] += xb * w.z; a1[3] += xb * w.w;
    }
    int ra = row0 + rl, rb = ra + 24;
    if (ra < NN)
        *(float4*)&g_feat2[ra * 40 + tc * 4] = make_float4(a0[0], a0[1], a0[2], a0[3]);
    if (rb < NN)
        *(float4*)&g_feat2[rb * 40 + tc * 4] = make_float4(a1[0], a1[1], a1[2], a1[3]);
}

// ---------------- layer2 attention coefficients ------------------------------
__global__ void k_coef2(const float* __restrict__ al, const float* __restrict__ ar) {
    int v = blockIdx.x * blockDim.x + threadIdx.x;
    if (v >= NN) return;
    const float* f = g_feat2 + v * 40;
    float el = 0.f, er = 0.f;
    #pragma unroll
    for (int j = 0; j < 40; j++) {
        float x = f[j];
        el += x * al[j];
        er += x * ar[j];
    }
    g_el2[v] = el;
    g_er2[v] = er;
}

// ---------------- layer2 fused softmax+aggregate (one warp per dst) ----------
__global__ void __launch_bounds__(256) k_node2(const float* __restrict__ b2,
                                               float* __restrict__ out) {
    int v = (blockIdx.x * blockDim.x + threadIdx.x) >> 5;
    if (v >= NN) return;
    int lane = threadIdx.x & 31;
    int beg = g_off[v], end = g_off[v + 1];
    float erv = g_er2[v];

    float denom = 0.f, acc0 = 0.f, acc1 = 0.f;
    int s0 = (beg < end) ? g_csrc[beg] : 0;
    float eln = (beg < end) ? g_el2[s0] : 0.f;
    float f0n = (beg < end) ? g_feat2[s0 * 40 + lane] : 0.f;
    float f1n = (beg < end && lane < 8) ? g_feat2[s0 * 40 + 32 + lane] : 0.f;
    for (int p = beg; p < end; p++) {
        float elc = eln, f0c = f0n, f1c = f1n;
        int sn = (p + 1 < end) ? g_csrc[p + 1] : 0;
        if (p + 1 < end) {
            eln = g_el2[sn];
            f0n = g_feat2[sn * 40 + lane];
            if (lane < 8) f1n = g_feat2[sn * 40 + 32 + lane];
        }
        float e = elc + erv;
        e = (e > 0.f) ? e : 0.2f * e;
        float w = __expf(e);
        denom += w;
        acc0 += w * f0c;
        acc1 += w * f1c;
    }
    float inv = 1.f / (denom + 1e-9f);
    out[v * 40 + lane] = acc0 * inv + b2[lane];
    if (lane < 8) out[v * 40 + 32 + lane] = acc1 * inv + b2[32 + lane];
}

// ---------------- launch ------------------------------------------------------
extern "C" void kernel_launch(void* const* d_in, const int* in_sizes, int n_in,
                              void* d_out, int out_size) {
    const float* features = (const float*)d_in[0];
    const int*   esrc     = (const int*)d_in[1];
    const int*   edst     = (const int*)d_in[2];
    const float* W1       = (const float*)d_in[3];
    const float* al1      = (const float*)d_in[4];
    const float* ar1      = (const float*)d_in[5];
    const float* b1       = (const float*)d_in[6];
    const float* W2       = (const float*)d_in[7];
    const float* al2      = (const float*)d_in[8];
    const float* ar2      = (const float*)d_in[9];
    const float* b2       = (const float*)d_in[10];
    float* out = (float*)d_out;

    k_zero<<<(NN + 255) / 256, 256>>>();
    k_count<<<(EE / 4 + 255) / 256, 256>>>(edst);
    k_scanA<<<NSB, SCAN_B>>>();
    k_scanB<<<1, 32>>>();
    k_scanC<<<(NN + 255) / 256, 256>>>();
    k_scatter<<<(EE / 4 + 255) / 256, 256>>>(esrc, edst);

    k_gemm1<<<(NN + 63) / 64, 256>>>(features, W1, al1, ar1);
    k_node1<<<(NN * 32 + 255) / 256, 256>>>(b1);

    k_gemm2<<<(NN + 47) / 48, 240>>>(W2);
    k_coef2<<<(NN + 255) / 256, 256>>>(al2, ar2);
    k_node2<<<(NN * 32 + 255) / 256, 256>>>(b2, out);
}